// round 1
// baseline (speedup 1.0000x reference)
#include <cuda_runtime.h>
#include <cstdint>

typedef unsigned long long ULL;

// ---------------- static device scratch ----------------
__device__ float g_K[33554432];        // [2][4096(k)][4096(p)]  (symmetric, stored full)
__device__ float g_feat[2 * 4096 * 8]; // [n][p][8]: vy,vx,vr,vg,vb,s,0,0  (s = 0.5*|v|^2)
__device__ float g_U[2 * 4096 * 21];   // [n][p][c]
__device__ float g_q[2 * 4096 * 21];   // [n][p][c]
__device__ float g_qcp[2 * 21 * 4096]; // [n][c][p]
__device__ float g_qbf[2 * 4096 * 21]; // [n][p][c] accumulator (zeroed between iters)
__device__ float g_tmp[2 * 21 * 4096]; // y-pass result [n][c][p]
__device__ float g_qsf[2 * 21 * 4096]; // spatial filter result [n][c][p]
__device__ float g_h[71];              // separable 1D gaussian

// ---------------- helpers ----------------
__device__ __forceinline__ void ffma2(ULL& d, ULL a, ULL b) {
    asm("fma.rn.f32x2 %0, %1, %2, %0;" : "+l"(d) : "l"(a), "l"(b));
}
__device__ __forceinline__ float ull_lo(ULL v) { return __uint_as_float((unsigned)(v & 0xffffffffu)); }
__device__ __forceinline__ float ull_hi(ULL v) { return __uint_as_float((unsigned)(v >> 32)); }

// exp(t) for t <= ~0 via FMA-pipe exp2 (no MUFU). rel err < 1e-5.
__device__ __forceinline__ float fast_exp_neg(float t) {
    float x = t * 1.4426950408889634f;   // log2(e)
    x = fmaxf(x, -126.0f);
    float fl = floorf(x);
    float f  = x - fl;
    float p  = 1.5403530393381609e-4f;
    p = fmaf(p, f, 1.3333558146428443e-3f);
    p = fmaf(p, f, 9.6181291076284770e-3f);
    p = fmaf(p, f, 5.5504108664821580e-2f);
    p = fmaf(p, f, 2.4022650695910071e-1f);
    p = fmaf(p, f, 6.9314718055994531e-1f);
    p = fmaf(p, f, 1.0f);
    int e = (int)fl;
    return p * __int_as_float((e + 127) << 23);
}

// ---------------- 1D gaussian extraction ----------------
__global__ void prep_h_kernel(const float* __restrict__ gk) {
    int i = threadIdx.x;
    if (i < 71) {
        // gk[0,0,35,i] / sqrt(gk[0,0,35,35]) = normalized 1D kernel
        g_h[i] = gk[35 * 71 + i] * rsqrtf(gk[35 * 71 + 35]);
    }
}

// ---------------- init: feats, U, q0 ----------------
__global__ void init_kernel(const float* __restrict__ unary,
                            const float* __restrict__ ref,
                            const float* __restrict__ kstd) {
    int idx = blockIdx.x * 256 + threadIdx.x;      // 0..8191
    if (idx >= 8192) return;
    int n = idx >> 12;
    int p = idx & 4095;
    int y = p >> 6, x = p & 63;

    float vy = (float)y / kstd[0];
    float vx = (float)x / kstd[1];
    float vr = ref[(n * 3 + 0) * 4096 + p] / kstd[2];
    float vg = ref[(n * 3 + 1) * 4096 + p] / kstd[3];
    float vb = ref[(n * 3 + 2) * 4096 + p] / kstd[4];
    float s = 0.5f * (vy * vy + vx * vx + vr * vr + vg * vg + vb * vb);
    float* fp = g_feat + (size_t)idx * 8;
    fp[0] = vy; fp[1] = vx; fp[2] = vr; fp[3] = vg; fp[4] = vb; fp[5] = s; fp[6] = 0.f; fp[7] = 0.f;

    float u[21];
    float m = -1e30f;
    #pragma unroll
    for (int c = 0; c < 21; ++c) {
        float v = unary[(n * 21 + c) * 4096 + p];
        v = fminf(fmaxf(v, 1e-5f), 1.0f);
        u[c] = __logf(v);
        g_U[idx * 21 + c] = u[c];
        m = fmaxf(m, u[c]);
    }
    float sum = 0.f;
    #pragma unroll
    for (int c = 0; c < 21; ++c) { u[c] = __expf(u[c] - m); sum += u[c]; }
    float inv = 1.0f / sum;
    #pragma unroll
    for (int c = 0; c < 21; ++c) {
        float qv = u[c] * inv;
        g_q[idx * 21 + c] = qv;
        g_qcp[(n * 21 + c) * 4096 + p] = qv;
        g_qbf[idx * 21 + c] = 0.f;
    }
}

// ---------------- K build: K[n][k][p] = exp(dot - s_k - s_p) ----------------
// grid (4 p-chunks, 32 k-chunks, 2 batches), 256 threads, 4 p per thread
__global__ void kbuild_kernel() {
    __shared__ float4 sk[128][2];
    const int n = blockIdx.z;
    const int kbase = blockIdx.y * 128;
    const int p0 = blockIdx.x * 1024 + threadIdx.x * 4;

    // stage k-row feats into smem
    {
        int idx = threadIdx.x;           // 256 entries = 128 rows x 2 halves
        int row = idx >> 1, half = idx & 1;
        sk[row][half] = *reinterpret_cast<const float4*>(
            g_feat + (size_t)(n * 4096 + kbase + row) * 8 + half * 4);
    }
    __syncthreads();

    // own 4 p feats in registers
    float vy[4], vx[4], vr[4], vg[4], vb[4], sp[4];
    #pragma unroll
    for (int r = 0; r < 4; ++r) {
        const float* fp = g_feat + (size_t)(n * 4096 + p0 + r) * 8;
        float4 a = *reinterpret_cast<const float4*>(fp);
        float4 b = *reinterpret_cast<const float4*>(fp + 4);
        vy[r] = a.x; vx[r] = a.y; vr[r] = a.z; vg[r] = a.w; vb[r] = b.x; sp[r] = b.y;
    }

    float* kout = g_K + ((size_t)n << 24) + (size_t)kbase * 4096 + p0;
    for (int kk = 0; kk < 128; ++kk) {
        float4 f0 = sk[kk][0];
        float4 f1 = sk[kk][1];
        float e[4];
        #pragma unroll
        for (int r = 0; r < 4; ++r) {
            float t = -(sp[r] + f1.y);
            t = fmaf(vy[r], f0.x, t);
            t = fmaf(vx[r], f0.y, t);
            t = fmaf(vr[r], f0.z, t);
            t = fmaf(vg[r], f0.w, t);
            t = fmaf(vb[r], f1.x, t);
            e[r] = fast_exp_neg(t);
        }
        *reinterpret_cast<float4*>(kout) = make_float4(e[0], e[1], e[2], e[3]);
        kout += 4096;
    }
}

// ---------------- separable spatial conv ----------------
__global__ void convY_kernel() {
    __shared__ float hs[71];
    if (threadIdx.x < 71) hs[threadIdx.x] = g_h[threadIdx.x];
    __syncthreads();
    int img = blockIdx.x;                       // 0..41 = n*21+c
    int pix = blockIdx.y * 256 + threadIdx.x;
    int y = pix >> 6, x = pix & 63;
    const float* in = g_qcp + (size_t)img * 4096;
    int t0 = max(0, 35 - y), t1 = min(70, 98 - y);
    float a0 = 0.f, a1 = 0.f, a2 = 0.f, a3 = 0.f;
    int t = t0;
    for (; t + 3 <= t1; t += 4) {
        a0 = fmaf(hs[t],     in[(y + t - 35) * 64 + x], a0);
        a1 = fmaf(hs[t + 1], in[(y + t - 34) * 64 + x], a1);
        a2 = fmaf(hs[t + 2], in[(y + t - 33) * 64 + x], a2);
        a3 = fmaf(hs[t + 3], in[(y + t - 32) * 64 + x], a3);
    }
    for (; t <= t1; ++t) a0 = fmaf(hs[t], in[(y + t - 35) * 64 + x], a0);
    g_tmp[(size_t)img * 4096 + pix] = (a0 + a1) + (a2 + a3);
}

__global__ void convX_kernel() {
    __shared__ float hs[71];
    if (threadIdx.x < 71) hs[threadIdx.x] = g_h[threadIdx.x];
    __syncthreads();
    int img = blockIdx.x;
    int pix = blockIdx.y * 256 + threadIdx.x;
    int y = pix >> 6, x = pix & 63;
    const float* in = g_tmp + (size_t)img * 4096;
    int t0 = max(0, 35 - x), t1 = min(70, 98 - x);
    float a0 = 0.f, a1 = 0.f, a2 = 0.f, a3 = 0.f;
    int t = t0;
    for (; t + 3 <= t1; t += 4) {
        a0 = fmaf(hs[t],     in[y * 64 + x + t - 35], a0);
        a1 = fmaf(hs[t + 1], in[y * 64 + x + t - 34], a1);
        a2 = fmaf(hs[t + 2], in[y * 64 + x + t - 33], a2);
        a3 = fmaf(hs[t + 3], in[y * 64 + x + t - 32], a3);
    }
    for (; t <= t1; ++t) a0 = fmaf(hs[t], in[y * 64 + x + t - 35], a0);
    g_qsf[(size_t)img * 4096 + pix] = (a0 + a1) + (a2 + a3);
}

// ---------------- GEMM: qbf[n][p][c] += sum_k K[n][k][p] * q[n][k][c] ----------------
// grid (4 p-blocks, 32 k-splits, 2 batches); 256 thr; thread owns 4 p-rows (2 f32x2 pairs)
__global__ void __launch_bounds__(256, 2) gemm_kernel() {
    __shared__ float4 qs[128][11];   // [kk][j]: {q[k][2j], q[k][2j], q[k][2j+1], q[k][2j+1]}
    const int n = blockIdx.z;
    const int kbase = blockIdx.y * 128;
    const int p0 = blockIdx.x * 1024 + threadIdx.x * 4;
    const float* qn = g_q + (size_t)n * 4096 * 21;

    for (int idx = threadIdx.x; idx < 128 * 11; idx += 256) {
        int kk = idx / 11, j = idx - kk * 11;
        const float* qp = qn + (size_t)(kbase + kk) * 21 + 2 * j;
        float v0 = qp[0];
        float v1 = (j < 10) ? qp[1] : 0.f;
        qs[kk][j] = make_float4(v0, v0, v1, v1);
    }
    __syncthreads();

    ULL acc[44];
    #pragma unroll
    for (int i = 0; i < 44; ++i) acc[i] = 0ull;

    const float* kp = g_K + ((size_t)n << 24) + (size_t)kbase * 4096 + p0;
    #pragma unroll 2
    for (int kk = 0; kk < 128; ++kk) {
        ulonglong2 kv = *reinterpret_cast<const ulonglong2*>(kp);  // rows p0..p0+3
        kp += 4096;
        #pragma unroll
        for (int j = 0; j < 11; ++j) {
            ulonglong2 qq = *reinterpret_cast<const ulonglong2*>(&qs[kk][j]);
            ffma2(acc[4 * j + 0], kv.x, qq.x);
            ffma2(acc[4 * j + 1], kv.y, qq.x);
            ffma2(acc[4 * j + 2], kv.x, qq.y);
            ffma2(acc[4 * j + 3], kv.y, qq.y);
        }
    }

    float* ob = g_qbf + (size_t)(n * 4096 + p0) * 21;
    #pragma unroll
    for (int j = 0; j < 11; ++j) {
        int c0 = 2 * j;
        atomicAdd(ob + c0,      ull_lo(acc[4 * j]));
        atomicAdd(ob + 21 + c0, ull_hi(acc[4 * j]));
        atomicAdd(ob + 42 + c0, ull_lo(acc[4 * j + 1]));
        atomicAdd(ob + 63 + c0, ull_hi(acc[4 * j + 1]));
        if (j < 10) {
            int c1 = c0 + 1;
            atomicAdd(ob + c1,      ull_lo(acc[4 * j + 2]));
            atomicAdd(ob + 21 + c1, ull_hi(acc[4 * j + 2]));
            atomicAdd(ob + 42 + c1, ull_lo(acc[4 * j + 3]));
            atomicAdd(ob + 63 + c1, ull_hi(acc[4 * j + 3]));
        }
    }
}

// ---------------- epilogue: combine + softmax (and reset qbf) ----------------
__global__ void epilogue_kernel(int last, float* __restrict__ out) {
    int idx = blockIdx.x * 256 + threadIdx.x;   // 0..8191
    if (idx >= 8192) return;
    int n = idx >> 12;
    int p = idx & 4095;
    const float* up = g_U + (size_t)idx * 21;
    float* bf = g_qbf + (size_t)idx * 21;
    const float* sf = g_qsf + (size_t)n * 21 * 4096 + p;

    float l[21];
    float m = -1e30f;
    #pragma unroll
    for (int c = 0; c < 21; ++c) {
        l[c] = up[c] + 4.0f * bf[c] + 2.0f * sf[(size_t)c * 4096];
        bf[c] = 0.f;
        m = fmaxf(m, l[c]);
    }
    float sum = 0.f;
    #pragma unroll
    for (int c = 0; c < 21; ++c) { l[c] = __expf(l[c] - m); sum += l[c]; }
    float inv = 1.0f / sum;
    #pragma unroll
    for (int c = 0; c < 21; ++c) {
        float qv = l[c] * inv;
        g_q[(size_t)idx * 21 + c] = qv;
        g_qcp[(size_t)(n * 21 + c) * 4096 + p] = qv;
        if (last) out[(size_t)(n * 21 + c) * 4096 + p] = qv;
    }
}

// ---------------- host launcher ----------------
extern "C" void kernel_launch(void* const* d_in, const int* in_sizes, int n_in,
                              void* d_out, int out_size) {
    const float* unary = nullptr;
    const float* ref = nullptr;
    const float* gk = nullptr;
    const float* kstd = nullptr;
    for (int i = 0; i < n_in; ++i) {
        switch (in_sizes[i]) {
            case 172032: unary = (const float*)d_in[i]; break;
            case 24576:  ref   = (const float*)d_in[i]; break;
            case 105861: gk    = (const float*)d_in[i]; break;
            case 5:      kstd  = (const float*)d_in[i]; break;
            default: break;
        }
    }
    float* out = (float*)d_out;

    prep_h_kernel<<<1, 128>>>(gk);
    init_kernel<<<32, 256>>>(unary, ref, kstd);
    kbuild_kernel<<<dim3(4, 32, 2), 256>>>();

    for (int it = 0; it < 5; ++it) {
        convY_kernel<<<dim3(42, 16), 256>>>();
        convX_kernel<<<dim3(42, 16), 256>>>();
        gemm_kernel<<<dim3(4, 32, 2), 256>>>();
        epilogue_kernel<<<32, 256>>>(it == 4 ? 1 : 0, out);
    }
}

// round 2
// speedup vs baseline: 1.0989x; 1.0989x over previous
#include <cuda_runtime.h>
#include <cstdint>

typedef unsigned long long ULL;

// ---------------- static device scratch ----------------
__device__ float g_K[33554432];        // [2][4096(k)][4096(p)]
__device__ float g_feat[2 * 4096 * 8]; // [n][p][8]: vy,vx,vr,vg,vb (x sqrt(log2e)), s*log2e
__device__ float g_U[2 * 4096 * 21];   // [n][p][c]
__device__ float g_q[2 * 4096 * 21];   // [n][p][c]
__device__ float g_qcp[2 * 21 * 4096]; // [n][c][p]
__device__ float g_part[16 * 2 * 4096 * 24]; // GEMM k-split partials [s][n][p][24]
__device__ float g_tmp[2 * 21 * 4096]; // y-pass result [n][c][p]
__device__ float g_qsf[2 * 21 * 4096]; // spatial filter result [n][c][p]
__device__ float g_h[71];              // separable 1D gaussian

// ---------------- f32x2 helpers ----------------
__device__ __forceinline__ ULL fma2v(ULL a, ULL b, ULL c) {
    ULL d; asm("fma.rn.f32x2 %0, %1, %2, %3;" : "=l"(d) : "l"(a), "l"(b), "l"(c)); return d;
}
__device__ __forceinline__ ULL add2v(ULL a, ULL b) {
    ULL d; asm("add.rn.f32x2 %0, %1, %2;" : "=l"(d) : "l"(a), "l"(b)); return d;
}
__device__ __forceinline__ ULL mul2v(ULL a, ULL b) {
    ULL d; asm("mul.rn.f32x2 %0, %1, %2;" : "=l"(d) : "l"(a), "l"(b)); return d;
}
__device__ __forceinline__ ULL dupf(float v) {
    ULL r; asm("mov.b64 %0, {%1, %1};" : "=l"(r) : "f"(v)); return r;
}
__device__ __forceinline__ ULL packf(float a, float b) {
    ULL r; asm("mov.b64 %0, {%1, %2};" : "=l"(r) : "f"(a), "f"(b)); return r;
}
__device__ __forceinline__ ULL packi(int a, int b) {
    ULL r; asm("mov.b64 %0, {%1, %2};" : "=l"(r) : "r"(a), "r"(b)); return r;
}
__device__ __forceinline__ void unpacki(ULL v, int& a, int& b) {
    asm("mov.b64 {%0, %1}, %2;" : "=r"(a), "=r"(b) : "l"(v));
}

// pair 2^x for x <= ~1 (log2-domain input). FMA-pipe only, no MUFU, no F2I.
__device__ __forceinline__ ULL exp2_pair(ULL x) {
    ULL z  = add2v(x, dupf(12582912.0f));            // round-to-nearest int in mantissa
    ULL fl = add2v(z, dupf(-12582912.0f));
    ULL f  = fma2v(fl, dupf(-1.0f), x);              // frac in [-0.5, 0.5]
    ULL p  = dupf(1.5403530393381608e-4f);
    p = fma2v(p, f, dupf(1.3333558146428443e-3f));
    p = fma2v(p, f, dupf(9.618129107628477e-3f));
    p = fma2v(p, f, dupf(5.550410866482158e-2f));
    p = fma2v(p, f, dupf(2.402265069591007e-1f));
    p = fma2v(p, f, dupf(6.931471805599453e-1f));
    p = fma2v(p, f, dupf(1.0f));
    int zl, zh; unpacki(z, zl, zh);
    int el = max(zl - 0x4B3FFF81, 0) << 23;          // (xi + 127) << 23, clamped
    int eh = max(zh - 0x4B3FFF81, 0) << 23;
    return mul2v(p, packi(el, eh));
}

// ---------------- 1D gaussian extraction ----------------
__global__ void prep_h_kernel(const float* __restrict__ gk) {
    int i = threadIdx.x;
    if (i < 71) g_h[i] = gk[35 * 71 + i] * rsqrtf(gk[35 * 71 + 35]);
}

// ---------------- init: feats (log2e-folded), U, q0 ----------------
__global__ void init_kernel(const float* __restrict__ unary,
                            const float* __restrict__ ref,
                            const float* __restrict__ kstd) {
    int idx = blockIdx.x * 256 + threadIdx.x;
    if (idx >= 8192) return;
    int n = idx >> 12;
    int p = idx & 4095;
    int y = p >> 6, x = p & 63;

    const float SQL2E = 1.2011224087864498f;  // sqrt(log2(e))
    float vy = SQL2E * (float)y / kstd[0];
    float vx = SQL2E * (float)x / kstd[1];
    float vr = SQL2E * ref[(n * 3 + 0) * 4096 + p] / kstd[2];
    float vg = SQL2E * ref[(n * 3 + 1) * 4096 + p] / kstd[3];
    float vb = SQL2E * ref[(n * 3 + 2) * 4096 + p] / kstd[4];
    float s = 0.5f * (vy * vy + vx * vx + vr * vr + vg * vg + vb * vb);
    float* fp = g_feat + (size_t)idx * 8;
    fp[0] = vy; fp[1] = vx; fp[2] = vr; fp[3] = vg; fp[4] = vb; fp[5] = s; fp[6] = 0.f; fp[7] = 0.f;

    float u[21];
    float m = -1e30f;
    #pragma unroll
    for (int c = 0; c < 21; ++c) {
        float v = unary[(n * 21 + c) * 4096 + p];
        v = fminf(fmaxf(v, 1e-5f), 1.0f);
        u[c] = __logf(v);
        g_U[(size_t)idx * 21 + c] = u[c];
        m = fmaxf(m, u[c]);
    }
    float sum = 0.f;
    #pragma unroll
    for (int c = 0; c < 21; ++c) { u[c] = __expf(u[c] - m); sum += u[c]; }
    float inv = __fdividef(1.0f, sum);
    #pragma unroll
    for (int c = 0; c < 21; ++c) {
        float qv = u[c] * inv;
        g_q[(size_t)idx * 21 + c] = qv;
        g_qcp[(size_t)(n * 21 + c) * 4096 + p] = qv;
    }
}

// ---------------- K build: K[n][k][p] = 2^(dot' - s'_k - s'_p) ----------------
__global__ void __launch_bounds__(256) kbuild_kernel() {
    __shared__ float4 sk[128][2];
    const int n = blockIdx.z;
    const int kbase = blockIdx.y * 128;
    const int tid = threadIdx.x;
    const int p0 = blockIdx.x * 1024 + tid * 4;

    {
        int row = tid >> 1, half = tid & 1;
        sk[row][half] = *reinterpret_cast<const float4*>(
            g_feat + (size_t)(n * 4096 + kbase + row) * 8 + half * 4);
    }
    __syncthreads();

    // own 4 p feats as 2 pairs
    ULL vy[2], vx[2], vr[2], vg[2], vb[2], ns[2];
    #pragma unroll
    for (int h = 0; h < 2; ++h) {
        const float* fa = g_feat + (size_t)(n * 4096 + p0 + 2 * h) * 8;
        float4 a0 = *reinterpret_cast<const float4*>(fa);
        float4 a1 = *reinterpret_cast<const float4*>(fa + 4);
        float4 b0 = *reinterpret_cast<const float4*>(fa + 8);
        float4 b1 = *reinterpret_cast<const float4*>(fa + 12);
        vy[h] = packf(a0.x, b0.x);
        vx[h] = packf(a0.y, b0.y);
        vr[h] = packf(a0.z, b0.z);
        vg[h] = packf(a0.w, b0.w);
        vb[h] = packf(a1.x, b1.x);
        ns[h] = packf(-a1.y, -b1.y);
    }

    float* kout = g_K + ((size_t)n << 24) + (size_t)kbase * 4096 + p0;
    for (int kk = 0; kk < 128; ++kk) {
        float4 f0 = sk[kk][0];
        float4 f1 = sk[kk][1];
        ULL dy = dupf(f0.x), dx = dupf(f0.y), dr = dupf(f0.z);
        ULL dg = dupf(f0.w), db = dupf(f1.x), dk = dupf(-f1.y);
        ulonglong2 ov;
        #pragma unroll
        for (int h = 0; h < 2; ++h) {
            ULL t = add2v(ns[h], dk);
            t = fma2v(vy[h], dy, t);
            t = fma2v(vx[h], dx, t);
            t = fma2v(vr[h], dr, t);
            t = fma2v(vg[h], dg, t);
            t = fma2v(vb[h], db, t);
            ULL e = exp2_pair(t);
            if (h == 0) ov.x = e; else ov.y = e;
        }
        *reinterpret_cast<ulonglong2*>(kout) = ov;
        kout += 4096;
    }
}

// ---------------- separable spatial conv (smem tiles) ----------------
__global__ void convY_kernel() {
    __shared__ float sIn[64][17];
    __shared__ float hs[72];
    int img = blockIdx.x;                 // 0..41
    int x0 = blockIdx.y * 16;
    int tid = threadIdx.x;                // 128
    if (tid < 71) hs[tid] = g_h[tid];
    const float* in = g_qcp + (size_t)img * 4096;
    for (int idx = tid; idx < 1024; idx += 128) {
        int y = idx >> 4, xc = idx & 15;
        sIn[y][xc] = in[y * 64 + x0 + xc];
    }
    __syncthreads();
    int xc = tid & 15;
    int y0 = (tid >> 4) * 8;
    float a[8] = {0, 0, 0, 0, 0, 0, 0, 0};
    int glo = max(0, y0 - 35), ghi = min(63, y0 + 42);
    for (int g = glo; g <= ghi; ++g) {
        float v = sIn[g][xc];
        int base = g - y0 + 35;
        #pragma unroll
        for (int o = 0; o < 8; ++o) {
            int t = base - o;
            if (t >= 0 && t <= 70) a[o] = fmaf(hs[t], v, a[o]);
        }
    }
    float* tp = g_tmp + (size_t)img * 4096 + x0 + xc;
    #pragma unroll
    for (int o = 0; o < 8; ++o) tp[(y0 + o) * 64] = a[o];
}

__global__ void convX_kernel() {
    __shared__ float sIn[16][65];
    __shared__ float hs[72];
    int img = blockIdx.x;
    int r0 = blockIdx.y * 16;             // 16 rows
    int tid = threadIdx.x;                // 128
    if (tid < 71) hs[tid] = g_h[tid];
    const float* in = g_tmp + (size_t)img * 4096;
    for (int idx = tid; idx < 1024; idx += 128) {
        int r = idx >> 6, x = idx & 63;
        sIn[r][x] = in[(r0 + r) * 64 + x];
    }
    __syncthreads();
    int row = tid & 15;
    int x0o = (tid >> 4) * 8;
    float a[8] = {0, 0, 0, 0, 0, 0, 0, 0};
    int glo = max(0, x0o - 35), ghi = min(63, x0o + 42);
    for (int g = glo; g <= ghi; ++g) {
        float v = sIn[row][g];
        int base = g - x0o + 35;
        #pragma unroll
        for (int o = 0; o < 8; ++o) {
            int t = base - o;
            if (t >= 0 && t <= 70) a[o] = fmaf(hs[t], v, a[o]);
        }
    }
    float* op = g_qsf + (size_t)img * 4096 + (r0 + row) * 64 + x0o;
    #pragma unroll
    for (int o = 0; o < 8; ++o) op[o] = a[o];
}

// ---------------- GEMM: part[s][n][p][c] = sum_{k in split s} K[n][k][p] * q[n][k][c] ----
// grid (4 p-blocks, 16 k-splits, 2 batches); 256 thr; thread owns 4 p x 21 c.
// Channel-paired FFMA2: q pairs straight from smem (broadcast), K duplicated in regs.
__global__ void __launch_bounds__(256) gemm_kernel() {
    __shared__ float qs[256][32];
    const int n = blockIdx.z;
    const int kbase = blockIdx.y * 256;
    const int tid = threadIdx.x;
    const int p0 = blockIdx.x * 1024 + tid * 4;

    const float* qn = g_q + (size_t)(n * 4096 + kbase) * 21;
    for (int idx = tid; idx < 8192; idx += 256) {
        int kk = idx >> 5, c = idx & 31;
        qs[kk][c] = (c < 21) ? qn[kk * 21 + c] : 0.f;
    }
    __syncthreads();

    ULL acc[44];
    #pragma unroll
    for (int i = 0; i < 44; ++i) acc[i] = 0ull;

    const float* kp = g_K + ((size_t)n << 24) + (size_t)kbase * 4096 + p0;
    float4 kv = __ldcs(reinterpret_cast<const float4*>(kp));
    float4 kw = __ldcs(reinterpret_cast<const float4*>(kp + 4096));
    kp += 2 * 4096;

    #pragma unroll 2
    for (int kk = 0; kk < 256; ++kk) {
        float4 kn;
        if (kk < 254) kn = __ldcs(reinterpret_cast<const float4*>(kp));
        else kn = make_float4(0.f, 0.f, 0.f, 0.f);
        kp += 4096;

        ULL kd0 = dupf(kv.x), kd1 = dupf(kv.y), kd2 = dupf(kv.z), kd3 = dupf(kv.w);
        const ULL* qrow = reinterpret_cast<const ULL*>(qs[kk]);
        #pragma unroll
        for (int j = 0; j < 11; ++j) {
            ULL qq = qrow[j];
            acc[j * 4 + 0] = fma2v(kd0, qq, acc[j * 4 + 0]);
            acc[j * 4 + 1] = fma2v(kd1, qq, acc[j * 4 + 1]);
            acc[j * 4 + 2] = fma2v(kd2, qq, acc[j * 4 + 2]);
            acc[j * 4 + 3] = fma2v(kd3, qq, acc[j * 4 + 3]);
        }
        kv = kw; kw = kn;
    }

    // store partials: [s][n][p][24]
    float* pb = g_part + ((size_t)(blockIdx.y * 2 + n) * 4096 + p0) * 24;
    #pragma unroll
    for (int r = 0; r < 4; ++r) {
        float* row = pb + r * 24;
        #pragma unroll
        for (int jj = 0; jj < 5; ++jj) {
            ulonglong2 v;
            v.x = acc[(2 * jj) * 4 + r];
            v.y = acc[(2 * jj + 1) * 4 + r];
            *reinterpret_cast<ulonglong2*>(row + jj * 4) = v;
        }
        *reinterpret_cast<ULL*>(row + 20) = acc[40 + r];
    }
}

// ---------------- epilogue: reduce partials + combine + softmax (warp per pixel) ----
__global__ void epilogue_kernel(int last, float* __restrict__ out) {
    int w = (blockIdx.x * blockDim.x + threadIdx.x) >> 5;   // global warp id = n*4096+p
    int lane = threadIdx.x & 31;
    int n = w >> 12, p = w & 4095;
    bool act = lane < 21;

    float acc = 0.f;
    if (act) {
        const float* pp = g_part + ((size_t)(n * 4096 + p)) * 24 + lane;
        #pragma unroll
        for (int s = 0; s < 16; ++s) acc += pp[(size_t)s * 2 * 4096 * 24];
    }

    float l = -1e30f;
    if (act) {
        float u = g_U[(size_t)w * 21 + lane];
        float sf = g_qsf[(size_t)(n * 21 + lane) * 4096 + p];
        l = u + 4.0f * acc + 2.0f * sf;
    }
    float m = l;
    #pragma unroll
    for (int off = 16; off > 0; off >>= 1)
        m = fmaxf(m, __shfl_xor_sync(0xffffffffu, m, off));
    float e = act ? __expf(l - m) : 0.f;
    float ssum = e;
    #pragma unroll
    for (int off = 16; off > 0; off >>= 1)
        ssum += __shfl_xor_sync(0xffffffffu, ssum, off);
    float qv = __fdividef(e, ssum);
    if (act) {
        g_q[(size_t)w * 21 + lane] = qv;
        g_qcp[(size_t)(n * 21 + lane) * 4096 + p] = qv;
        if (last) out[(size_t)(n * 21 + lane) * 4096 + p] = qv;
    }
}

// ---------------- host launcher ----------------
extern "C" void kernel_launch(void* const* d_in, const int* in_sizes, int n_in,
                              void* d_out, int out_size) {
    const float* unary = nullptr;
    const float* ref = nullptr;
    const float* gk = nullptr;
    const float* kstd = nullptr;
    for (int i = 0; i < n_in; ++i) {
        switch (in_sizes[i]) {
            case 172032: unary = (const float*)d_in[i]; break;
            case 24576:  ref   = (const float*)d_in[i]; break;
            case 105861: gk    = (const float*)d_in[i]; break;
            case 5:      kstd  = (const float*)d_in[i]; break;
            default: break;
        }
    }
    float* out = (float*)d_out;

    prep_h_kernel<<<1, 128>>>(gk);
    init_kernel<<<32, 256>>>(unary, ref, kstd);
    kbuild_kernel<<<dim3(4, 32, 2), 256>>>();

    for (int it = 0; it < 5; ++it) {
        convY_kernel<<<dim3(42, 4), 128>>>();
        convX_kernel<<<dim3(42, 4), 128>>>();
        gemm_kernel<<<dim3(4, 16, 2), 256>>>();
        epilogue_kernel<<<1024, 256>>>(it == 4 ? 1 : 0, out);
    }
}

// round 7
// speedup vs baseline: 1.1887x; 1.0817x over previous
#include <cuda_runtime.h>
#include <cstdint>

typedef unsigned long long ULL;

// ---------------- static device scratch ----------------
__device__ float g_K[33554432];        // [2][4096(k)][4096(p)]
__device__ float g_feat[2 * 4096 * 8]; // [n][p][8]
__device__ float g_U[2 * 4096 * 21];   // [n][p][c]
__device__ float g_q[2 * 4096 * 21];   // [n][p][c]
__device__ float g_qcp[2 * 21 * 4096]; // [n][c][p]
__device__ float g_part[16 * 2 * 4096 * 24]; // GEMM k-split partials
__device__ float g_tmp[2 * 21 * 4096]; // y-pass result
__device__ float g_qsf[2 * 21 * 4096]; // spatial filter result
__device__ float g_h[71];              // separable 1D gaussian

// ---------------- f32x2 helpers ----------------
__device__ __forceinline__ ULL fma2v(ULL a, ULL b, ULL c) {
    ULL d; asm("fma.rn.f32x2 %0, %1, %2, %3;" : "=l"(d) : "l"(a), "l"(b), "l"(c)); return d;
}
__device__ __forceinline__ ULL add2v(ULL a, ULL b) {
    ULL d; asm("add.rn.f32x2 %0, %1, %2;" : "=l"(d) : "l"(a), "l"(b)); return d;
}
__device__ __forceinline__ ULL mul2v(ULL a, ULL b) {
    ULL d; asm("mul.rn.f32x2 %0, %1, %2;" : "=l"(d) : "l"(a), "l"(b)); return d;
}
__device__ __forceinline__ ULL dupf(float v) {
    ULL r; asm("mov.b64 %0, {%1, %1};" : "=l"(r) : "f"(v)); return r;
}
__device__ __forceinline__ ULL packf(float a, float b) {
    ULL r; asm("mov.b64 %0, {%1, %2};" : "=l"(r) : "f"(a), "f"(b)); return r;
}
__device__ __forceinline__ ULL packi(int a, int b) {
    ULL r; asm("mov.b64 %0, {%1, %2};" : "=l"(r) : "r"(a), "r"(b)); return r;
}
__device__ __forceinline__ void unpacki(ULL v, int& a, int& b) {
    asm("mov.b64 {%0, %1}, %2;" : "=r"(a), "=r"(b) : "l"(v));
}

// pair 2^x, FMA-pipe only
__device__ __forceinline__ ULL exp2_pair(ULL x) {
    ULL z  = add2v(x, dupf(12582912.0f));
    ULL fl = add2v(z, dupf(-12582912.0f));
    ULL f  = fma2v(fl, dupf(-1.0f), x);
    ULL p  = dupf(1.5403530393381608e-4f);
    p = fma2v(p, f, dupf(1.3333558146428443e-3f));
    p = fma2v(p, f, dupf(9.618129107628477e-3f));
    p = fma2v(p, f, dupf(5.550410866482158e-2f));
    p = fma2v(p, f, dupf(2.402265069591007e-1f));
    p = fma2v(p, f, dupf(6.931471805599453e-1f));
    p = fma2v(p, f, dupf(1.0f));
    int zl, zh; unpacki(z, zl, zh);
    int el = max(zl - 0x4B3FFF81, 0) << 23;
    int eh = max(zh - 0x4B3FFF81, 0) << 23;
    return mul2v(p, packi(el, eh));
}

// ---------------- init: h, feats (log2e-folded), U, q0 ----------------
__global__ void init_kernel(const float* __restrict__ unary,
                            const float* __restrict__ ref,
                            const float* __restrict__ gk,
                            const float* __restrict__ kstd) {
    if (blockIdx.x == 0 && threadIdx.x < 71)
        g_h[threadIdx.x] = gk[35 * 71 + threadIdx.x] * rsqrtf(gk[35 * 71 + 35]);

    int idx = blockIdx.x * 256 + threadIdx.x;
    if (idx >= 8192) return;
    int n = idx >> 12;
    int p = idx & 4095;
    int y = p >> 6, x = p & 63;

    const float SQL2E = 1.2011224087864498f;  // sqrt(log2(e))
    float vy = SQL2E * (float)y / kstd[0];
    float vx = SQL2E * (float)x / kstd[1];
    float vr = SQL2E * ref[(n * 3 + 0) * 4096 + p] / kstd[2];
    float vg = SQL2E * ref[(n * 3 + 1) * 4096 + p] / kstd[3];
    float vb = SQL2E * ref[(n * 3 + 2) * 4096 + p] / kstd[4];
    float s = 0.5f * (vy * vy + vx * vx + vr * vr + vg * vg + vb * vb);
    float* fp = g_feat + (size_t)idx * 8;
    fp[0] = vy; fp[1] = vx; fp[2] = vr; fp[3] = vg; fp[4] = vb; fp[5] = s; fp[6] = 0.f; fp[7] = 0.f;

    float u[21];
    float m = -1e30f;
    #pragma unroll
    for (int c = 0; c < 21; ++c) {
        float v = unary[(n * 21 + c) * 4096 + p];
        v = fminf(fmaxf(v, 1e-5f), 1.0f);
        u[c] = __logf(v);
        g_U[(size_t)idx * 21 + c] = u[c];
        m = fmaxf(m, u[c]);
    }
    float sum = 0.f;
    #pragma unroll
    for (int c = 0; c < 21; ++c) { u[c] = __expf(u[c] - m); sum += u[c]; }
    float inv = __fdividef(1.0f, sum);
    #pragma unroll
    for (int c = 0; c < 21; ++c) {
        float qv = u[c] * inv;
        g_q[(size_t)idx * 21 + c] = qv;
        g_qcp[(size_t)(n * 21 + c) * 4096 + p] = qv;
    }
}

// ---------------- K build ----------------
__global__ void __launch_bounds__(256) kbuild_kernel() {
    __shared__ float4 sk[128][2];
    const int n = blockIdx.z;
    const int kbase = blockIdx.y * 128;
    const int tid = threadIdx.x;
    const int p0 = blockIdx.x * 1024 + tid * 4;

    {
        int row = tid >> 1, half = tid & 1;
        sk[row][half] = *reinterpret_cast<const float4*>(
            g_feat + (size_t)(n * 4096 + kbase + row) * 8 + half * 4);
    }
    __syncthreads();

    ULL vy[2], vx[2], vr[2], vg[2], vb[2], ns[2];
    #pragma unroll
    for (int h = 0; h < 2; ++h) {
        const float* fa = g_feat + (size_t)(n * 4096 + p0 + 2 * h) * 8;
        float4 a0 = *reinterpret_cast<const float4*>(fa);
        float4 a1 = *reinterpret_cast<const float4*>(fa + 4);
        float4 b0 = *reinterpret_cast<const float4*>(fa + 8);
        float4 b1 = *reinterpret_cast<const float4*>(fa + 12);
        vy[h] = packf(a0.x, b0.x);
        vx[h] = packf(a0.y, b0.y);
        vr[h] = packf(a0.z, b0.z);
        vg[h] = packf(a0.w, b0.w);
        vb[h] = packf(a1.x, b1.x);
        ns[h] = packf(-a1.y, -b1.y);
    }

    float* kout = g_K + ((size_t)n << 24) + (size_t)kbase * 4096 + p0;
    for (int kk = 0; kk < 128; ++kk) {
        float4 f0 = sk[kk][0];
        float4 f1 = sk[kk][1];
        ULL dy = dupf(f0.x), dx = dupf(f0.y), dr = dupf(f0.z);
        ULL dg = dupf(f0.w), db = dupf(f1.x), dk = dupf(-f1.y);
        ulonglong2 ov;
        #pragma unroll
        for (int h = 0; h < 2; ++h) {
            ULL t = add2v(ns[h], dk);
            t = fma2v(vy[h], dy, t);
            t = fma2v(vx[h], dx, t);
            t = fma2v(vr[h], dr, t);
            t = fma2v(vg[h], dg, t);
            t = fma2v(vb[h], db, t);
            ULL e = exp2_pair(t);
            if (h == 0) ov.x = e; else ov.y = e;
        }
        *reinterpret_cast<ulonglong2*>(kout) = ov;
        kout += 4096;
    }
}

// ---------------- separable spatial conv: predicate-free padded smem tiles ----------
// convY: tile 32y x 8x, input 102x8 zero-padded. grid (42, 16), 256 thr, 1 out/thread.
__global__ void __launch_bounds__(256) convY_kernel() {
    __shared__ float s[102 * 8];
    __shared__ float hs[71];
    int img = blockIdx.x;
    int tile = blockIdx.y;
    int y0 = (tile >> 3) * 32, x0 = (tile & 7) * 8;
    int tid = threadIdx.x;
    if (tid < 71) hs[tid] = g_h[tid];
    const float* in = g_qcp + (size_t)img * 4096;
    #pragma unroll
    for (int base = 0; base < 816; base += 256) {
        int idx = base + tid;
        if (idx < 816) {
            int g = idx >> 3, xc = idx & 7;
            int y = y0 - 35 + g;
            s[idx] = (y >= 0 && y < 64) ? in[y * 64 + x0 + xc] : 0.f;
        }
    }
    __syncthreads();
    int yc = tid >> 3, xc = tid & 7;
    const float* sp = s + yc * 8 + xc;
    float a0 = 0.f, a1 = 0.f, a2 = 0.f, a3 = 0.f;
    #pragma unroll
    for (int t = 0; t < 68; t += 4) {
        a0 = fmaf(hs[t],     sp[t * 8],       a0);
        a1 = fmaf(hs[t + 1], sp[(t + 1) * 8], a1);
        a2 = fmaf(hs[t + 2], sp[(t + 2) * 8], a2);
        a3 = fmaf(hs[t + 3], sp[(t + 3) * 8], a3);
    }
    a0 = fmaf(hs[68], sp[68 * 8], a0);
    a1 = fmaf(hs[69], sp[69 * 8], a1);
    a2 = fmaf(hs[70], sp[70 * 8], a2);
    g_tmp[(size_t)img * 4096 + (y0 + yc) * 64 + x0 + xc] = (a0 + a1) + (a2 + a3);
}

// convX: tile 8y x 32x, input 8x104 zero-padded. grid (42, 16), 256 thr, 1 out/thread.
__global__ void __launch_bounds__(256) convX_kernel() {
    __shared__ float s[8 * 104];
    __shared__ float hs[71];
    int img = blockIdx.x;
    int tile = blockIdx.y;
    int y0 = (tile >> 1) * 8, x0 = (tile & 1) * 32;
    int tid = threadIdx.x;
    if (tid < 71) hs[tid] = g_h[tid];
    const float* in = g_tmp + (size_t)img * 4096;
    {
        int w = tid >> 5, lane = tid & 31;
        #pragma unroll
        for (int c0 = 0; c0 < 104; c0 += 32) {
            int c = c0 + lane;
            int x = x0 - 35 + c;
            if (c < 104)
                s[w * 104 + c] = (c < 102 && x >= 0 && x < 64) ? in[(y0 + w) * 64 + x] : 0.f;
        }
    }
    __syncthreads();
    int yc = tid >> 5, xc = tid & 31;
    const float* sp = s + yc * 104 + xc;
    float a0 = 0.f, a1 = 0.f, a2 = 0.f, a3 = 0.f;
    #pragma unroll
    for (int t = 0; t < 68; t += 4) {
        a0 = fmaf(hs[t],     sp[t],     a0);
        a1 = fmaf(hs[t + 1], sp[t + 1], a1);
        a2 = fmaf(hs[t + 2], sp[t + 2], a2);
        a3 = fmaf(hs[t + 3], sp[t + 3], a3);
    }
    a0 = fmaf(hs[68], sp[68], a0);
    a1 = fmaf(hs[69], sp[69], a1);
    a2 = fmaf(hs[70], sp[70], a2);
    g_qsf[(size_t)img * 4096 + (y0 + yc) * 64 + x0 + xc] = (a0 + a1) + (a2 + a3);
}

// ---------------- GEMM ----------------
__global__ void __launch_bounds__(256) gemm_kernel() {
    __shared__ float qs[256][32];
    const int n = blockIdx.z;
    const int kbase = blockIdx.y * 256;
    const int tid = threadIdx.x;
    const int p0 = blockIdx.x * 1024 + tid * 4;

    const float* qn = g_q + (size_t)(n * 4096 + kbase) * 21;
    for (int idx = tid; idx < 8192; idx += 256) {
        int kk = idx >> 5, c = idx & 31;
        qs[kk][c] = (c < 21) ? qn[kk * 21 + c] : 0.f;
    }
    __syncthreads();

    ULL acc[44];
    #pragma unroll
    for (int i = 0; i < 44; ++i) acc[i] = 0ull;

    const float* kp = g_K + ((size_t)n << 24) + (size_t)kbase * 4096 + p0;
    float4 kv = __ldcs(reinterpret_cast<const float4*>(kp));
    float4 kw = __ldcs(reinterpret_cast<const float4*>(kp + 4096));
    kp += 2 * 4096;

    #pragma unroll 2
    for (int kk = 0; kk < 256; ++kk) {
        float4 kn;
        if (kk < 254) kn = __ldcs(reinterpret_cast<const float4*>(kp));
        else kn = make_float4(0.f, 0.f, 0.f, 0.f);
        kp += 4096;

        ULL kd0 = dupf(kv.x), kd1 = dupf(kv.y), kd2 = dupf(kv.z), kd3 = dupf(kv.w);
        const ULL* qrow = reinterpret_cast<const ULL*>(qs[kk]);
        #pragma unroll
        for (int j = 0; j < 11; ++j) {
            ULL qq = qrow[j];
            acc[j * 4 + 0] = fma2v(kd0, qq, acc[j * 4 + 0]);
            acc[j * 4 + 1] = fma2v(kd1, qq, acc[j * 4 + 1]);
            acc[j * 4 + 2] = fma2v(kd2, qq, acc[j * 4 + 2]);
            acc[j * 4 + 3] = fma2v(kd3, qq, acc[j * 4 + 3]);
        }
        kv = kw; kw = kn;
    }

    float* pb = g_part + ((size_t)(blockIdx.y * 2 + n) * 4096 + p0) * 24;
    #pragma unroll
    for (int r = 0; r < 4; ++r) {
        float* row = pb + r * 24;
        #pragma unroll
        for (int jj = 0; jj < 5; ++jj) {
            ulonglong2 v;
            v.x = acc[(2 * jj) * 4 + r];
            v.y = acc[(2 * jj + 1) * 4 + r];
            *reinterpret_cast<ulonglong2*>(row + jj * 4) = v;
        }
        *reinterpret_cast<ULL*>(row + 20) = acc[40 + r];
    }
}

// ---------------- epilogue ----------------
__global__ void epilogue_kernel(int last, float* __restrict__ out) {
    int w = (blockIdx.x * blockDim.x + threadIdx.x) >> 5;
    int lane = threadIdx.x & 31;
    int n = w >> 12, p = w & 4095;
    bool act = lane < 21;

    float acc = 0.f;
    if (act) {
        const float* pp = g_part + ((size_t)(n * 4096 + p)) * 24 + lane;
        #pragma unroll
        for (int s = 0; s < 16; ++s) acc += pp[(size_t)s * 2 * 4096 * 24];
    }

    float l = -1e30f;
    if (act) {
        float u = g_U[(size_t)w * 21 + lane];
        float sf = g_qsf[(size_t)(n * 21 + lane) * 4096 + p];
        l = u + 4.0f * acc + 2.0f * sf;
    }
    float m = l;
    #pragma unroll
    for (int off = 16; off > 0; off >>= 1)
        m = fmaxf(m, __shfl_xor_sync(0xffffffffu, m, off));
    float e = act ? __expf(l - m) : 0.f;
    float ssum = e;
    #pragma unroll
    for (int off = 16; off > 0; off >>= 1)
        ssum += __shfl_xor_sync(0xffffffffu, ssum, off);
    float qv = __fdividef(e, ssum);
    if (act) {
        g_q[(size_t)w * 21 + lane] = qv;
        g_qcp[(size_t)(n * 21 + lane) * 4096 + p] = qv;
        if (last) out[(size_t)(n * 21 + lane) * 4096 + p] = qv;
    }
}

// ---------------- host launcher ----------------
extern "C" void kernel_launch(void* const* d_in, const int* in_sizes, int n_in,
                              void* d_out, int out_size) {
    const float* unary = nullptr;
    const float* ref = nullptr;
    const float* gk = nullptr;
    const float* kstd = nullptr;
    for (int i = 0; i < n_in; ++i) {
        switch (in_sizes[i]) {
            case 172032: unary = (const float*)d_in[i]; break;
            case 24576:  ref   = (const float*)d_in[i]; break;
            case 105861: gk    = (const float*)d_in[i]; break;
            case 5:      kstd  = (const float*)d_in[i]; break;
            default: break;
        }
    }
    float* out = (float*)d_out;

    init_kernel<<<32, 256>>>(unary, ref, gk, kstd);
    kbuild_kernel<<<dim3(4, 32, 2), 256>>>();

    for (int it = 0; it < 5; ++it) {
        convY_kernel<<<dim3(42, 16), 256>>>();
        convX_kernel<<<dim3(42, 16), 256>>>();
        gemm_kernel<<<dim3(4, 16, 2), 256>>>();
        epilogue_kernel<<<1024, 256>>>(it == 4 ? 1 : 0, out);
    }
}

// round 10
// speedup vs baseline: 1.2885x; 1.0840x over previous
#include <cuda_runtime.h>
#include <cstdint>

typedef unsigned long long ULL;

// ---------------- static device scratch ----------------
__device__ float g_K[33554432];        // [2][4096(k)][4096(p)]
__device__ float g_feat[2 * 4096 * 8]; // [n][p][8]
__device__ float g_U[2 * 4096 * 21];   // [n][p][c]
__device__ float g_q[2 * 4096 * 21];   // [n][p][c]
__device__ float g_qcp[2 * 21 * 4096]; // [n][c][p]
__device__ float g_part[32 * 2 * 4096 * 24]; // GEMM k-split partials [s][n][p][24]
__device__ float g_tmp[2 * 21 * 4096]; // y-pass result
__device__ float g_qsf[2 * 21 * 4096]; // spatial filter result
__device__ float g_h[71];              // separable 1D gaussian

// ---------------- f32x2 helpers ----------------
__device__ __forceinline__ ULL fma2v(ULL a, ULL b, ULL c) {
    ULL d; asm("fma.rn.f32x2 %0, %1, %2, %3;" : "=l"(d) : "l"(a), "l"(b), "l"(c)); return d;
}
__device__ __forceinline__ ULL add2v(ULL a, ULL b) {
    ULL d; asm("add.rn.f32x2 %0, %1, %2;" : "=l"(d) : "l"(a), "l"(b)); return d;
}
__device__ __forceinline__ ULL mul2v(ULL a, ULL b) {
    ULL d; asm("mul.rn.f32x2 %0, %1, %2;" : "=l"(d) : "l"(a), "l"(b)); return d;
}
__device__ __forceinline__ ULL dupf(float v) {
    ULL r; asm("mov.b64 %0, {%1, %1};" : "=l"(r) : "f"(v)); return r;
}
__device__ __forceinline__ ULL packf(float a, float b) {
    ULL r; asm("mov.b64 %0, {%1, %2};" : "=l"(r) : "f"(a), "f"(b)); return r;
}
__device__ __forceinline__ ULL packi(int a, int b) {
    ULL r; asm("mov.b64 %0, {%1, %2};" : "=l"(r) : "r"(a), "r"(b)); return r;
}
__device__ __forceinline__ void unpacki(ULL v, int& a, int& b) {
    asm("mov.b64 {%0, %1}, %2;" : "=r"(a), "=r"(b) : "l"(v));
}

// pair 2^x, FMA-pipe only
__device__ __forceinline__ ULL exp2_pair(ULL x) {
    ULL z  = add2v(x, dupf(12582912.0f));
    ULL fl = add2v(z, dupf(-12582912.0f));
    ULL f  = fma2v(fl, dupf(-1.0f), x);
    ULL p  = dupf(1.5403530393381608e-4f);
    p = fma2v(p, f, dupf(1.3333558146428443e-3f));
    p = fma2v(p, f, dupf(9.618129107628477e-3f));
    p = fma2v(p, f, dupf(5.550410866482158e-2f));
    p = fma2v(p, f, dupf(2.402265069591007e-1f));
    p = fma2v(p, f, dupf(6.931471805599453e-1f));
    p = fma2v(p, f, dupf(1.0f));
    int zl, zh; unpacki(z, zl, zh);
    int el = max(zl - 0x4B3FFF81, 0) << 23;
    int eh = max(zh - 0x4B3FFF81, 0) << 23;
    return mul2v(p, packi(el, eh));
}

// ---------------- init: h, feats (log2e-folded), U, q0 ----------------
__global__ void init_kernel(const float* __restrict__ unary,
                            const float* __restrict__ ref,
                            const float* __restrict__ gk,
                            const float* __restrict__ kstd) {
    if (blockIdx.x == 0 && threadIdx.x < 71)
        g_h[threadIdx.x] = gk[35 * 71 + threadIdx.x] * rsqrtf(gk[35 * 71 + 35]);

    int idx = blockIdx.x * 256 + threadIdx.x;
    if (idx >= 8192) return;
    int n = idx >> 12;
    int p = idx & 4095;
    int y = p >> 6, x = p & 63;

    const float SQL2E = 1.2011224087864498f;  // sqrt(log2(e))
    float vy = SQL2E * (float)y / kstd[0];
    float vx = SQL2E * (float)x / kstd[1];
    float vr = SQL2E * ref[(n * 3 + 0) * 4096 + p] / kstd[2];
    float vg = SQL2E * ref[(n * 3 + 1) * 4096 + p] / kstd[3];
    float vb = SQL2E * ref[(n * 3 + 2) * 4096 + p] / kstd[4];
    float s = 0.5f * (vy * vy + vx * vx + vr * vr + vg * vg + vb * vb);
    float* fp = g_feat + (size_t)idx * 8;
    fp[0] = vy; fp[1] = vx; fp[2] = vr; fp[3] = vg; fp[4] = vb; fp[5] = s; fp[6] = 0.f; fp[7] = 0.f;

    float u[21];
    float m = -1e30f;
    #pragma unroll
    for (int c = 0; c < 21; ++c) {
        float v = unary[(n * 21 + c) * 4096 + p];
        v = fminf(fmaxf(v, 1e-5f), 1.0f);
        u[c] = __logf(v);
        g_U[(size_t)idx * 21 + c] = u[c];
        m = fmaxf(m, u[c]);
    }
    float sum = 0.f;
    #pragma unroll
    for (int c = 0; c < 21; ++c) { u[c] = __expf(u[c] - m); sum += u[c]; }
    float inv = __fdividef(1.0f, sum);
    #pragma unroll
    for (int c = 0; c < 21; ++c) {
        float qv = u[c] * inv;
        g_q[(size_t)idx * 21 + c] = qv;
        g_qcp[(size_t)(n * 21 + c) * 4096 + p] = qv;
    }
}

// ---------------- K build ----------------
__global__ void __launch_bounds__(256) kbuild_kernel() {
    __shared__ float4 sk[128][2];
    const int n = blockIdx.z;
    const int kbase = blockIdx.y * 128;
    const int tid = threadIdx.x;
    const int p0 = blockIdx.x * 1024 + tid * 4;

    {
        int row = tid >> 1, half = tid & 1;
        sk[row][half] = *reinterpret_cast<const float4*>(
            g_feat + (size_t)(n * 4096 + kbase + row) * 8 + half * 4);
    }
    __syncthreads();

    ULL vy[2], vx[2], vr[2], vg[2], vb[2], ns[2];
    #pragma unroll
    for (int h = 0; h < 2; ++h) {
        const float* fa = g_feat + (size_t)(n * 4096 + p0 + 2 * h) * 8;
        float4 a0 = *reinterpret_cast<const float4*>(fa);
        float4 a1 = *reinterpret_cast<const float4*>(fa + 4);
        float4 b0 = *reinterpret_cast<const float4*>(fa + 8);
        float4 b1 = *reinterpret_cast<const float4*>(fa + 12);
        vy[h] = packf(a0.x, b0.x);
        vx[h] = packf(a0.y, b0.y);
        vr[h] = packf(a0.z, b0.z);
        vg[h] = packf(a0.w, b0.w);
        vb[h] = packf(a1.x, b1.x);
        ns[h] = packf(-a1.y, -b1.y);
    }

    float* kout = g_K + ((size_t)n << 24) + (size_t)kbase * 4096 + p0;
    for (int kk = 0; kk < 128; ++kk) {
        float4 f0 = sk[kk][0];
        float4 f1 = sk[kk][1];
        ULL dy = dupf(f0.x), dx = dupf(f0.y), dr = dupf(f0.z);
        ULL dg = dupf(f0.w), db = dupf(f1.x), dk = dupf(-f1.y);
        ulonglong2 ov;
        #pragma unroll
        for (int h = 0; h < 2; ++h) {
            ULL t = add2v(ns[h], dk);
            t = fma2v(vy[h], dy, t);
            t = fma2v(vx[h], dx, t);
            t = fma2v(vr[h], dr, t);
            t = fma2v(vg[h], dg, t);
            t = fma2v(vb[h], db, t);
            ULL e = exp2_pair(t);
            if (h == 0) ov.x = e; else ov.y = e;
        }
        *reinterpret_cast<ulonglong2*>(kout) = ov;
        kout += 4096;
    }
}

// ---------------- separable spatial conv: predicate-free padded smem tiles ----------
__global__ void __launch_bounds__(256) convY_kernel() {
    __shared__ float s[102 * 8];
    __shared__ float hs[71];
    int img = blockIdx.x;
    int tile = blockIdx.y;
    int y0 = (tile >> 3) * 32, x0 = (tile & 7) * 8;
    int tid = threadIdx.x;
    if (tid < 71) hs[tid] = g_h[tid];
    const float* in = g_qcp + (size_t)img * 4096;
    #pragma unroll
    for (int base = 0; base < 816; base += 256) {
        int idx = base + tid;
        if (idx < 816) {
            int g = idx >> 3, xc = idx & 7;
            int y = y0 - 35 + g;
            s[idx] = (y >= 0 && y < 64) ? in[y * 64 + x0 + xc] : 0.f;
        }
    }
    __syncthreads();
    int yc = tid >> 3, xc = tid & 7;
    const float* sp = s + yc * 8 + xc;
    float a0 = 0.f, a1 = 0.f, a2 = 0.f, a3 = 0.f;
    #pragma unroll
    for (int t = 0; t < 68; t += 4) {
        a0 = fmaf(hs[t],     sp[t * 8],       a0);
        a1 = fmaf(hs[t + 1], sp[(t + 1) * 8], a1);
        a2 = fmaf(hs[t + 2], sp[(t + 2) * 8], a2);
        a3 = fmaf(hs[t + 3], sp[(t + 3) * 8], a3);
    }
    a0 = fmaf(hs[68], sp[68 * 8], a0);
    a1 = fmaf(hs[69], sp[69 * 8], a1);
    a2 = fmaf(hs[70], sp[70 * 8], a2);
    g_tmp[(size_t)img * 4096 + (y0 + yc) * 64 + x0 + xc] = (a0 + a1) + (a2 + a3);
}

__global__ void __launch_bounds__(256) convX_kernel() {
    __shared__ float s[8 * 104];
    __shared__ float hs[71];
    int img = blockIdx.x;
    int tile = blockIdx.y;
    int y0 = (tile >> 1) * 8, x0 = (tile & 1) * 32;
    int tid = threadIdx.x;
    if (tid < 71) hs[tid] = g_h[tid];
    const float* in = g_tmp + (size_t)img * 4096;
    {
        int w = tid >> 5, lane = tid & 31;
        #pragma unroll
        for (int c0 = 0; c0 < 104; c0 += 32) {
            int c = c0 + lane;
            int x = x0 - 35 + c;
            if (c < 104)
                s[w * 104 + c] = (c < 102 && x >= 0 && x < 64) ? in[(y0 + w) * 64 + x] : 0.f;
        }
    }
    __syncthreads();
    int yc = tid >> 5, xc = tid & 31;
    const float* sp = s + yc * 104 + xc;
    float a0 = 0.f, a1 = 0.f, a2 = 0.f, a3 = 0.f;
    #pragma unroll
    for (int t = 0; t < 68; t += 4) {
        a0 = fmaf(hs[t],     sp[t],     a0);
        a1 = fmaf(hs[t + 1], sp[t + 1], a1);
        a2 = fmaf(hs[t + 2], sp[t + 2], a2);
        a3 = fmaf(hs[t + 3], sp[t + 3], a3);
    }
    a0 = fmaf(hs[68], sp[68], a0);
    a1 = fmaf(hs[69], sp[69], a1);
    a2 = fmaf(hs[70], sp[70], a2);
    g_qsf[(size_t)img * 4096 + (y0 + yc) * 64 + x0 + xc] = (a0 + a1) + (a2 + a3);
}

// ---------------- GEMM: part[s][n][p][c] = sum_{k in split s} K[n][k][p] * q[n][k][c] ----
// grid (8 p-blocks, 32 k-splits, 2 batches), 256 thr, 2 p-rows per thread.
// Channel-paired FFMA2; depth-4 front-batched prefetch for DRAM MLP; default caching
// (K may be partially L2-resident across iterations).
__global__ void __launch_bounds__(256) gemm_kernel() {
    __shared__ float qs[128][32];
    const int n = blockIdx.z;
    const int kbase = blockIdx.y * 128;
    const int tid = threadIdx.x;
    const int p0 = blockIdx.x * 512 + tid * 2;

    const float* qn = g_q + (size_t)(n * 4096 + kbase) * 21;
    for (int idx = tid; idx < 4096; idx += 256) {
        int kk = idx >> 5, c = idx & 31;
        qs[kk][c] = (c < 21) ? qn[kk * 21 + c] : 0.f;
    }
    __syncthreads();

    ULL acc[22];
    #pragma unroll
    for (int i = 0; i < 22; ++i) acc[i] = 0ull;

    const float* __restrict__ kp = g_K + ((size_t)n << 24) + (size_t)kbase * 4096 + p0;

    float2 buf[4];
    #pragma unroll
    for (int i = 0; i < 4; ++i)
        buf[i] = *reinterpret_cast<const float2*>(kp + (size_t)i * 4096);

    for (int kk0 = 0; kk0 < 128; kk0 += 4) {
        float2 nxt[4];
        #pragma unroll
        for (int i = 0; i < 4; ++i) {
            int kkn = kk0 + 4 + i;
            nxt[i] = (kkn < 128) ? *reinterpret_cast<const float2*>(kp + (size_t)kkn * 4096)
                                 : make_float2(0.f, 0.f);
        }
        #pragma unroll
        for (int i = 0; i < 4; ++i) {
            ULL k0 = dupf(buf[i].x), k1 = dupf(buf[i].y);
            const ULL* qrow = reinterpret_cast<const ULL*>(qs[kk0 + i]);
            #pragma unroll
            for (int j = 0; j < 11; ++j) {
                ULL qq = qrow[j];
                acc[j * 2 + 0] = fma2v(k0, qq, acc[j * 2 + 0]);
                acc[j * 2 + 1] = fma2v(k1, qq, acc[j * 2 + 1]);
            }
        }
        #pragma unroll
        for (int i = 0; i < 4; ++i) buf[i] = nxt[i];
    }

    // store partials: [s][n][p][24], 2 rows of 24 floats
    float* pb = g_part + ((size_t)(blockIdx.y * 2 + n) * 4096 + p0) * 24;
    #pragma unroll
    for (int r = 0; r < 2; ++r) {
        float* row = pb + r * 24;
        #pragma unroll
        for (int jj = 0; jj < 5; ++jj) {
            ulonglong2 v;
            v.x = acc[(2 * jj) * 2 + r];
            v.y = acc[(2 * jj + 1) * 2 + r];
            *reinterpret_cast<ulonglong2*>(row + jj * 4) = v;
        }
        *reinterpret_cast<ULL*>(row + 20) = acc[40 / 2 + r];  // acc[20+r] = channel pair 10
    }
}

// ---------------- epilogue: reduce 32 partials + combine + softmax (warp/pixel) ----
__global__ void epilogue_kernel(int last, float* __restrict__ out) {
    int w = (blockIdx.x * blockDim.x + threadIdx.x) >> 5;
    int lane = threadIdx.x & 31;
    int n = w >> 12, p = w & 4095;
    bool act = lane < 21;

    float acc = 0.f;
    if (act) {
        const float* pp = g_part + ((size_t)(n * 4096 + p)) * 24 + lane;
        #pragma unroll
        for (int s = 0; s < 32; ++s) acc += pp[(size_t)s * 2 * 4096 * 24];
    }

    float l = -1e30f;
    if (act) {
        float u = g_U[(size_t)w * 21 + lane];
        float sf = g_qsf[(size_t)(n * 21 + lane) * 4096 + p];
        l = u + 4.0f * acc + 2.0f * sf;
    }
    float m = l;
    #pragma unroll
    for (int off = 16; off > 0; off >>= 1)
        m = fmaxf(m, __shfl_xor_sync(0xffffffffu, m, off));
    float e = act ? __expf(l - m) : 0.f;
    float ssum = e;
    #pragma unroll
    for (int off = 16; off > 0; off >>= 1)
        ssum += __shfl_xor_sync(0xffffffffu, ssum, off);
    float qv = __fdividef(e, ssum);
    if (act) {
        g_q[(size_t)w * 21 + lane] = qv;
        g_qcp[(size_t)(n * 21 + lane) * 4096 + p] = qv;
        if (last) out[(size_t)(n * 21 + lane) * 4096 + p] = qv;
    }
}

// ---------------- host launcher ----------------
extern "C" void kernel_launch(void* const* d_in, const int* in_sizes, int n_in,
                              void* d_out, int out_size) {
    const float* unary = nullptr;
    const float* ref = nullptr;
    const float* gk = nullptr;
    const float* kstd = nullptr;
    for (int i = 0; i < n_in; ++i) {
        switch (in_sizes[i]) {
            case 172032: unary = (const float*)d_in[i]; break;
            case 24576:  ref   = (const float*)d_in[i]; break;
            case 105861: gk    = (const float*)d_in[i]; break;
            case 5:      kstd  = (const float*)d_in[i]; break;
            default: break;
        }
    }
    float* out = (float*)d_out;

    init_kernel<<<32, 256>>>(unary, ref, gk, kstd);
    kbuild_kernel<<<dim3(4, 32, 2), 256>>>();

    for (int it = 0; it < 5; ++it) {
        convY_kernel<<<dim3(42, 16), 256>>>();
        convX_kernel<<<dim3(42, 16), 256>>>();
        gemm_kernel<<<dim3(8, 32, 2), 256>>>();
        epilogue_kernel<<<1024, 256>>>(it == 4 ? 1 : 0, out);
    }
}